// round 1
// baseline (speedup 1.0000x reference)
#include <cuda_runtime.h>
#include <math.h>

#define NROW 512
#define CZ 128
#define NPAIR (NROW * NROW)  /* 262144 */

// ---- scratch (device globals; no allocation inside kernel_launch) ----
__device__ float g_a[(size_t)NPAIR * CZ];
__device__ float g_b[(size_t)NPAIR * CZ];
__device__ float g_g[(size_t)NPAIR * CZ];
__device__ float g_t[(size_t)NPAIR * CZ];

__device__ __forceinline__ float sigmoidf_(float x) {
    return 1.0f / (1.0f + expf(-x));
}

__device__ __forceinline__ float warp_sum(float v) {
#pragma unroll
    for (int o = 16; o; o >>= 1) v += __shfl_xor_sync(0xffffffffu, v, o);
    return v;
}

// ============================================================================
// proj_kernel: per 32-row tile of flattened z [262144,128]:
//   LN(z) in smem, then GEMM against gate (and proj) weights, fused sigmoid.
// mode 0: a = sigmoid(zn@w_gate+b_gate) * (zn@w_proj+b_proj)  -> g_a
// mode 1: same -> g_b
// mode 2: g = sigmoid(zn@w_gate+b_gate)                       -> g_g
// ============================================================================
__global__ __launch_bounds__(256) void proj_kernel(
    const float* __restrict__ z,
    const float* __restrict__ lnw, const float* __restrict__ lnb,
    const float* __restrict__ w_proj, const float* __restrict__ b_proj,
    const float* __restrict__ w_gate, const float* __restrict__ b_gate,
    int mode)
{
    __shared__ float xs[32][CZ];
    __shared__ float ws[32][CZ];

    const int tid  = threadIdx.x;
    const int row0 = blockIdx.x * 32;

    // ---- load 32x128 z tile ----
#pragma unroll
    for (int v = 0; v < 4; ++v) {
        int lin = v * 256 + tid;          // float4 index in [0,1024)
        int r = lin >> 5, c4 = lin & 31;
        ((float4*)&xs[r][0])[c4] =
            ((const float4*)(z + (size_t)(row0 + r) * CZ))[c4];
    }
    __syncthreads();

    // ---- layernorm (one warp handles 4 rows) ----
    {
        const int lane = tid & 31, wid = tid >> 5;
        float lw0 = lnw[lane], lw1 = lnw[lane + 32], lw2 = lnw[lane + 64], lw3 = lnw[lane + 96];
        float lb0 = lnb[lane], lb1 = lnb[lane + 32], lb2 = lnb[lane + 64], lb3 = lnb[lane + 96];
#pragma unroll
        for (int r = 0; r < 4; ++r) {
            int row = wid * 4 + r;
            float x0 = xs[row][lane],      x1 = xs[row][lane + 32];
            float x2 = xs[row][lane + 64], x3 = xs[row][lane + 96];
            float m = warp_sum(x0 + x1 + x2 + x3) * (1.0f / 128.0f);
            float d0 = x0 - m, d1 = x1 - m, d2 = x2 - m, d3 = x3 - m;
            float var = warp_sum(d0 * d0 + d1 * d1 + d2 * d2 + d3 * d3) * (1.0f / 128.0f);
            float rs = rsqrtf(var + 1e-5f);
            xs[row][lane]      = d0 * rs * lw0 + lb0;
            xs[row][lane + 32] = d1 * rs * lw1 + lb1;
            xs[row][lane + 64] = d2 * rs * lw2 + lb2;
            xs[row][lane + 96] = d3 * rs * lw3 + lb3;
        }
    }
    __syncthreads();

    const int tc = tid & 31;   // column group: cols tc*4..tc*4+3
    const int tr = tid >> 5;   // row group:    rows tr*4..tr*4+3

    // ---- gate GEMM ----
    float accg[4][4];
#pragma unroll
    for (int rr = 0; rr < 4; ++rr)
#pragma unroll
        for (int cc = 0; cc < 4; ++cc) accg[rr][cc] = 0.0f;

#pragma unroll 1
    for (int kc = 0; kc < 4; ++kc) {
#pragma unroll
        for (int v = 0; v < 4; ++v) {
            int lin = v * 256 + tid;
            int r = lin >> 5, c4 = lin & 31;
            ((float4*)&ws[r][0])[c4] =
                ((const float4*)(w_gate + (size_t)(kc * 32 + r) * CZ))[c4];
        }
        __syncthreads();
#pragma unroll
        for (int k = 0; k < 32; ++k) {
            float4 wf = ((const float4*)&ws[k][0])[tc];
#pragma unroll
            for (int rr = 0; rr < 4; ++rr) {
                float xv = xs[tr * 4 + rr][kc * 32 + k];
                accg[rr][0] += xv * wf.x;
                accg[rr][1] += xv * wf.y;
                accg[rr][2] += xv * wf.z;
                accg[rr][3] += xv * wf.w;
            }
        }
        __syncthreads();
    }

    // ---- proj GEMM (modes 0/1) ----
    float accp[4][4];
#pragma unroll
    for (int rr = 0; rr < 4; ++rr)
#pragma unroll
        for (int cc = 0; cc < 4; ++cc) accp[rr][cc] = 0.0f;

    if (mode != 2) {
#pragma unroll 1
        for (int kc = 0; kc < 4; ++kc) {
#pragma unroll
            for (int v = 0; v < 4; ++v) {
                int lin = v * 256 + tid;
                int r = lin >> 5, c4 = lin & 31;
                ((float4*)&ws[r][0])[c4] =
                    ((const float4*)(w_proj + (size_t)(kc * 32 + r) * CZ))[c4];
            }
            __syncthreads();
#pragma unroll
            for (int k = 0; k < 32; ++k) {
                float4 wf = ((const float4*)&ws[k][0])[tc];
#pragma unroll
                for (int rr = 0; rr < 4; ++rr) {
                    float xv = xs[tr * 4 + rr][kc * 32 + k];
                    accp[rr][0] += xv * wf.x;
                    accp[rr][1] += xv * wf.y;
                    accp[rr][2] += xv * wf.z;
                    accp[rr][3] += xv * wf.w;
                }
            }
            __syncthreads();
        }
    }

    // ---- epilogue ----
    const int c = tc * 4;
    float4 bg = *(const float4*)(b_gate + c);
    float* outp = (mode == 0) ? g_a : (mode == 1) ? g_b : g_g;

    if (mode == 2) {
#pragma unroll
        for (int rr = 0; rr < 4; ++rr) {
            size_t row = (size_t)(row0 + tr * 4 + rr);
            float4 o;
            o.x = sigmoidf_(accg[rr][0] + bg.x);
            o.y = sigmoidf_(accg[rr][1] + bg.y);
            o.z = sigmoidf_(accg[rr][2] + bg.z);
            o.w = sigmoidf_(accg[rr][3] + bg.w);
            *(float4*)(outp + row * CZ + c) = o;
        }
    } else {
        float4 bp = *(const float4*)(b_proj + c);
#pragma unroll
        for (int rr = 0; rr < 4; ++rr) {
            size_t row = (size_t)(row0 + tr * 4 + rr);
            float4 o;
            o.x = sigmoidf_(accg[rr][0] + bg.x) * (accp[rr][0] + bp.x);
            o.y = sigmoidf_(accg[rr][1] + bg.y) * (accp[rr][1] + bp.y);
            o.z = sigmoidf_(accg[rr][2] + bg.z) * (accp[rr][2] + bp.z);
            o.w = sigmoidf_(accg[rr][3] + bg.w) * (accp[rr][3] + bp.w);
            *(float4*)(outp + row * CZ + c) = o;
        }
    }
}

// ============================================================================
// tri_kernel: t[i,j,c] = sum_k a[i,k,c] * b[j,k,c]
// Tile: 32 i x 32 j x 32 c per block; channels ride as float4 lanes.
// Thread: g4 = tid&7 (channel float4), q = tid>>3; qi=q&7 (4 i's), qj=q>>3 (8 j's).
// ============================================================================
__global__ __launch_bounds__(256, 1) void tri_kernel()
{
    __shared__ float4 as4[1024];  // [i(32)][k(4)][c4(8)]
    __shared__ float4 bs4[1024];

    const int tid = threadIdx.x;
    const int j0 = blockIdx.x * 32;
    const int i0 = blockIdx.y * 32;
    const int c0 = blockIdx.z * 32;

    const int g4 = tid & 7;
    const int q  = tid >> 3;
    const int qi = q & 7;   // i = i0 + qi*4 + ii
    const int qj = q >> 3;  // j = j0 + qj*8 + jj

    float4 acc[4][8];
#pragma unroll
    for (int ii = 0; ii < 4; ++ii)
#pragma unroll
        for (int jj = 0; jj < 8; ++jj)
            acc[ii][jj] = make_float4(0.f, 0.f, 0.f, 0.f);

#pragma unroll 1
    for (int k0 = 0; k0 < NROW; k0 += 4) {
#pragma unroll
        for (int v = 0; v < 4; ++v) {
            int lin = v * 256 + tid;                // 0..1023
            int c4 = lin & 7, kk = (lin >> 3) & 3, r = lin >> 5;
            as4[lin] = ((const float4*)(g_a +
                        ((size_t)(i0 + r) * NROW + (k0 + kk)) * CZ + c0))[c4];
            bs4[lin] = ((const float4*)(g_b +
                        ((size_t)(j0 + r) * NROW + (k0 + kk)) * CZ + c0))[c4];
        }
        __syncthreads();

#pragma unroll
        for (int kk = 0; kk < 4; ++kk) {
            float4 af[4];
#pragma unroll
            for (int ii = 0; ii < 4; ++ii)
                af[ii] = as4[((qi * 4 + ii) * 4 + kk) * 8 + g4];
            float4 bf[8];
#pragma unroll
            for (int jj = 0; jj < 8; ++jj)
                bf[jj] = bs4[((qj * 8 + jj) * 4 + kk) * 8 + g4];
#pragma unroll
            for (int ii = 0; ii < 4; ++ii)
#pragma unroll
                for (int jj = 0; jj < 8; ++jj) {
                    acc[ii][jj].x += af[ii].x * bf[jj].x;
                    acc[ii][jj].y += af[ii].y * bf[jj].y;
                    acc[ii][jj].z += af[ii].z * bf[jj].z;
                    acc[ii][jj].w += af[ii].w * bf[jj].w;
                }
        }
        __syncthreads();
    }

#pragma unroll
    for (int ii = 0; ii < 4; ++ii) {
        size_t i = (size_t)(i0 + qi * 4 + ii);
#pragma unroll
        for (int jj = 0; jj < 8; ++jj) {
            size_t j = (size_t)(j0 + qj * 8 + jj);
            *(float4*)(g_t + (i * NROW + j) * CZ + c0 + g4 * 4) = acc[ii][jj];
        }
    }
}

// ============================================================================
// final_kernel: out = g * (LN(t) @ w_z + b_z)
// ============================================================================
__global__ __launch_bounds__(256) void final_kernel(
    const float* __restrict__ lnw, const float* __restrict__ lnb,
    const float* __restrict__ w_z, const float* __restrict__ b_z,
    float* __restrict__ out)
{
    __shared__ float xs[32][CZ];
    __shared__ float ws[32][CZ];

    const int tid  = threadIdx.x;
    const int row0 = blockIdx.x * 32;

#pragma unroll
    for (int v = 0; v < 4; ++v) {
        int lin = v * 256 + tid;
        int r = lin >> 5, c4 = lin & 31;
        ((float4*)&xs[r][0])[c4] =
            ((const float4*)(g_t + (size_t)(row0 + r) * CZ))[c4];
    }
    __syncthreads();

    {
        const int lane = tid & 31, wid = tid >> 5;
        float lw0 = lnw[lane], lw1 = lnw[lane + 32], lw2 = lnw[lane + 64], lw3 = lnw[lane + 96];
        float lb0 = lnb[lane], lb1 = lnb[lane + 32], lb2 = lnb[lane + 64], lb3 = lnb[lane + 96];
#pragma unroll
        for (int r = 0; r < 4; ++r) {
            int row = wid * 4 + r;
            float x0 = xs[row][lane],      x1 = xs[row][lane + 32];
            float x2 = xs[row][lane + 64], x3 = xs[row][lane + 96];
            float m = warp_sum(x0 + x1 + x2 + x3) * (1.0f / 128.0f);
            float d0 = x0 - m, d1 = x1 - m, d2 = x2 - m, d3 = x3 - m;
            float var = warp_sum(d0 * d0 + d1 * d1 + d2 * d2 + d3 * d3) * (1.0f / 128.0f);
            float rs = rsqrtf(var + 1e-5f);
            xs[row][lane]      = d0 * rs * lw0 + lb0;
            xs[row][lane + 32] = d1 * rs * lw1 + lb1;
            xs[row][lane + 64] = d2 * rs * lw2 + lb2;
            xs[row][lane + 96] = d3 * rs * lw3 + lb3;
        }
    }
    __syncthreads();

    const int tc = tid & 31;
    const int tr = tid >> 5;

    float acc[4][4];
#pragma unroll
    for (int rr = 0; rr < 4; ++rr)
#pragma unroll
        for (int cc = 0; cc < 4; ++cc) acc[rr][cc] = 0.0f;

#pragma unroll 1
    for (int kc = 0; kc < 4; ++kc) {
#pragma unroll
        for (int v = 0; v < 4; ++v) {
            int lin = v * 256 + tid;
            int r = lin >> 5, c4 = lin & 31;
            ((float4*)&ws[r][0])[c4] =
                ((const float4*)(w_z + (size_t)(kc * 32 + r) * CZ))[c4];
        }
        __syncthreads();
#pragma unroll
        for (int k = 0; k < 32; ++k) {
            float4 wf = ((const float4*)&ws[k][0])[tc];
#pragma unroll
            for (int rr = 0; rr < 4; ++rr) {
                float xv = xs[tr * 4 + rr][kc * 32 + k];
                acc[rr][0] += xv * wf.x;
                acc[rr][1] += xv * wf.y;
                acc[rr][2] += xv * wf.z;
                acc[rr][3] += xv * wf.w;
            }
        }
        __syncthreads();
    }

    const int c = tc * 4;
    float4 bz = *(const float4*)(b_z + c);
#pragma unroll
    for (int rr = 0; rr < 4; ++rr) {
        size_t row = (size_t)(row0 + tr * 4 + rr);
        float4 gv = *(const float4*)(g_g + row * CZ + c);
        float4 o;
        o.x = gv.x * (acc[rr][0] + bz.x);
        o.y = gv.y * (acc[rr][1] + bz.y);
        o.z = gv.z * (acc[rr][2] + bz.z);
        o.w = gv.w * (acc[rr][3] + bz.w);
        *(float4*)(out + row * CZ + c) = o;
    }
}

// ============================================================================
// kernel_launch
// Inputs (metadata order): z, ln_in_w, ln_in_b, ln_out_w, ln_out_b,
//   w_ap, b_ap, w_ag, b_ag, w_bp, b_bp, w_bg, b_bg, w_g, b_g, w_z, b_z
// ============================================================================
extern "C" void kernel_launch(void* const* d_in, const int* in_sizes, int n_in,
                              void* d_out, int out_size)
{
    const float* z        = (const float*)d_in[0];
    const float* ln_in_w  = (const float*)d_in[1];
    const float* ln_in_b  = (const float*)d_in[2];
    const float* ln_out_w = (const float*)d_in[3];
    const float* ln_out_b = (const float*)d_in[4];
    const float* w_ap     = (const float*)d_in[5];
    const float* b_ap     = (const float*)d_in[6];
    const float* w_ag     = (const float*)d_in[7];
    const float* b_ag     = (const float*)d_in[8];
    const float* w_bp     = (const float*)d_in[9];
    const float* b_bp     = (const float*)d_in[10];
    const float* w_bg     = (const float*)d_in[11];
    const float* b_bg     = (const float*)d_in[12];
    const float* w_g      = (const float*)d_in[13];
    const float* b_g      = (const float*)d_in[14];
    const float* w_z      = (const float*)d_in[15];
    const float* b_z      = (const float*)d_in[16];
    float* out = (float*)d_out;

    const int nblk = NPAIR / 32;  // 8192

    proj_kernel<<<nblk, 256>>>(z, ln_in_w, ln_in_b, w_ap, b_ap, w_ag, b_ag, 0);
    proj_kernel<<<nblk, 256>>>(z, ln_in_w, ln_in_b, w_bp, b_bp, w_bg, b_bg, 1);
    proj_kernel<<<nblk, 256>>>(z, ln_in_w, ln_in_b, w_g,  b_g,  w_g,  b_g,  2);

    dim3 tgrid(NROW / 32, NROW / 32, CZ / 32);  // (16,16,4)
    tri_kernel<<<tgrid, 256>>>();

    final_kernel<<<nblk, 256>>>(ln_out_w, ln_out_b, w_z, b_z, out);
}

// round 2
// speedup vs baseline: 1.0058x; 1.0058x over previous
#include <cuda_runtime.h>
#include <math.h>

#define NROW 512
#define CZ 128
#define NPAIR (NROW * NROW)  /* 262144 */

// ---- scratch (device globals; no allocation inside kernel_launch) ----
__device__ float g_a[(size_t)NPAIR * CZ];
__device__ float g_b[(size_t)NPAIR * CZ];
__device__ float g_g[(size_t)NPAIR * CZ];
__device__ float g_t[(size_t)NPAIR * CZ];

__device__ __forceinline__ float sigmoidf_(float x) {
    return 1.0f / (1.0f + expf(-x));
}

__device__ __forceinline__ float warp_sum(float v) {
#pragma unroll
    for (int o = 16; o; o >>= 1) v += __shfl_xor_sync(0xffffffffu, v, o);
    return v;
}

// ============================================================================
// proj_kernel: per 32-row tile of flattened z [262144,128]:
//   LN(z) in smem, then GEMM against gate (and proj) weights, fused sigmoid.
// mode 0: a = sigmoid(zn@w_gate+b_gate) * (zn@w_proj+b_proj)  -> g_a
// mode 1: same -> g_b
// mode 2: g = sigmoid(zn@w_gate+b_gate)                       -> g_g
// ============================================================================
__global__ __launch_bounds__(256) void proj_kernel(
    const float* __restrict__ z,
    const float* __restrict__ lnw, const float* __restrict__ lnb,
    const float* __restrict__ w_proj, const float* __restrict__ b_proj,
    const float* __restrict__ w_gate, const float* __restrict__ b_gate,
    int mode)
{
    __shared__ float xs[32][CZ];
    __shared__ float ws[32][CZ];

    const int tid  = threadIdx.x;
    const int row0 = blockIdx.x * 32;

    // ---- load 32x128 z tile ----
#pragma unroll
    for (int v = 0; v < 4; ++v) {
        int lin = v * 256 + tid;          // float4 index in [0,1024)
        int r = lin >> 5, c4 = lin & 31;
        ((float4*)&xs[r][0])[c4] =
            ((const float4*)(z + (size_t)(row0 + r) * CZ))[c4];
    }
    __syncthreads();

    // ---- layernorm (one warp handles 4 rows) ----
    {
        const int lane = tid & 31, wid = tid >> 5;
        float lw0 = lnw[lane], lw1 = lnw[lane + 32], lw2 = lnw[lane + 64], lw3 = lnw[lane + 96];
        float lb0 = lnb[lane], lb1 = lnb[lane + 32], lb2 = lnb[lane + 64], lb3 = lnb[lane + 96];
#pragma unroll
        for (int r = 0; r < 4; ++r) {
            int row = wid * 4 + r;
            float x0 = xs[row][lane],      x1 = xs[row][lane + 32];
            float x2 = xs[row][lane + 64], x3 = xs[row][lane + 96];
            float m = warp_sum(x0 + x1 + x2 + x3) * (1.0f / 128.0f);
            float d0 = x0 - m, d1 = x1 - m, d2 = x2 - m, d3 = x3 - m;
            float var = warp_sum(d0 * d0 + d1 * d1 + d2 * d2 + d3 * d3) * (1.0f / 128.0f);
            float rs = rsqrtf(var + 1e-5f);
            xs[row][lane]      = d0 * rs * lw0 + lb0;
            xs[row][lane + 32] = d1 * rs * lw1 + lb1;
            xs[row][lane + 64] = d2 * rs * lw2 + lb2;
            xs[row][lane + 96] = d3 * rs * lw3 + lb3;
        }
    }
    __syncthreads();

    const int tc = tid & 31;   // column group: cols tc*4..tc*4+3
    const int tr = tid >> 5;   // row group:    rows tr*4..tr*4+3

    // ---- gate GEMM ----
    float accg[4][4];
#pragma unroll
    for (int rr = 0; rr < 4; ++rr)
#pragma unroll
        for (int cc = 0; cc < 4; ++cc) accg[rr][cc] = 0.0f;

#pragma unroll 1
    for (int kc = 0; kc < 4; ++kc) {
#pragma unroll
        for (int v = 0; v < 4; ++v) {
            int lin = v * 256 + tid;
            int r = lin >> 5, c4 = lin & 31;
            ((float4*)&ws[r][0])[c4] =
                ((const float4*)(w_gate + (size_t)(kc * 32 + r) * CZ))[c4];
        }
        __syncthreads();
#pragma unroll
        for (int k = 0; k < 32; ++k) {
            float4 wf = ((const float4*)&ws[k][0])[tc];
#pragma unroll
            for (int rr = 0; rr < 4; ++rr) {
                float xv = xs[tr * 4 + rr][kc * 32 + k];
                accg[rr][0] += xv * wf.x;
                accg[rr][1] += xv * wf.y;
                accg[rr][2] += xv * wf.z;
                accg[rr][3] += xv * wf.w;
            }
        }
        __syncthreads();
    }

    // ---- proj GEMM (modes 0/1) ----
    float accp[4][4];
#pragma unroll
    for (int rr = 0; rr < 4; ++rr)
#pragma unroll
        for (int cc = 0; cc < 4; ++cc) accp[rr][cc] = 0.0f;

    if (mode != 2) {
#pragma unroll 1
        for (int kc = 0; kc < 4; ++kc) {
#pragma unroll
            for (int v = 0; v < 4; ++v) {
                int lin = v * 256 + tid;
                int r = lin >> 5, c4 = lin & 31;
                ((float4*)&ws[r][0])[c4] =
                    ((const float4*)(w_proj + (size_t)(kc * 32 + r) * CZ))[c4];
            }
            __syncthreads();
#pragma unroll
            for (int k = 0; k < 32; ++k) {
                float4 wf = ((const float4*)&ws[k][0])[tc];
#pragma unroll
                for (int rr = 0; rr < 4; ++rr) {
                    float xv = xs[tr * 4 + rr][kc * 32 + k];
                    accp[rr][0] += xv * wf.x;
                    accp[rr][1] += xv * wf.y;
                    accp[rr][2] += xv * wf.z;
                    accp[rr][3] += xv * wf.w;
                }
            }
            __syncthreads();
        }
    }

    // ---- epilogue ----
    const int c = tc * 4;
    float4 bg = *(const float4*)(b_gate + c);
    float* outp = (mode == 0) ? g_a : (mode == 1) ? g_b : g_g;

    if (mode == 2) {
#pragma unroll
        for (int rr = 0; rr < 4; ++rr) {
            size_t row = (size_t)(row0 + tr * 4 + rr);
            float4 o;
            o.x = sigmoidf_(accg[rr][0] + bg.x);
            o.y = sigmoidf_(accg[rr][1] + bg.y);
            o.z = sigmoidf_(accg[rr][2] + bg.z);
            o.w = sigmoidf_(accg[rr][3] + bg.w);
            *(float4*)(outp + row * CZ + c) = o;
        }
    } else {
        float4 bp = *(const float4*)(b_proj + c);
#pragma unroll
        for (int rr = 0; rr < 4; ++rr) {
            size_t row = (size_t)(row0 + tr * 4 + rr);
            float4 o;
            o.x = sigmoidf_(accg[rr][0] + bg.x) * (accp[rr][0] + bp.x);
            o.y = sigmoidf_(accg[rr][1] + bg.y) * (accp[rr][1] + bp.y);
            o.z = sigmoidf_(accg[rr][2] + bg.z) * (accp[rr][2] + bp.z);
            o.w = sigmoidf_(accg[rr][3] + bg.w) * (accp[rr][3] + bp.w);
            *(float4*)(outp + row * CZ + c) = o;
        }
    }
}

// ============================================================================
// tri_kernel: t[i,j,c] = sum_k a[i,k,c] * b[j,k,c]
// Tile: 32 i x 32 j x 32 c per block; channels ride as float4 lanes.
// Thread: g4 = tid&7 (channel float4), q = tid>>3; qi=q&7 (4 i's), qj=q>>3 (8 j's).
// ============================================================================
__global__ __launch_bounds__(256, 1) void tri_kernel()
{
    __shared__ float4 as4[1024];  // [i(32)][k(4)][c4(8)]
    __shared__ float4 bs4[1024];

    const int tid = threadIdx.x;
    const int j0 = blockIdx.x * 32;
    const int i0 = blockIdx.y * 32;
    const int c0 = blockIdx.z * 32;

    const int g4 = tid & 7;
    const int q  = tid >> 3;
    const int qi = q & 7;   // i = i0 + qi*4 + ii
    const int qj = q >> 3;  // j = j0 + qj*8 + jj

    float4 acc[4][8];
#pragma unroll
    for (int ii = 0; ii < 4; ++ii)
#pragma unroll
        for (int jj = 0; jj < 8; ++jj)
            acc[ii][jj] = make_float4(0.f, 0.f, 0.f, 0.f);

#pragma unroll 1
    for (int k0 = 0; k0 < NROW; k0 += 4) {
#pragma unroll
        for (int v = 0; v < 4; ++v) {
            int lin = v * 256 + tid;                // 0..1023
            int c4 = lin & 7, kk = (lin >> 3) & 3, r = lin >> 5;
            as4[lin] = ((const float4*)(g_a +
                        ((size_t)(i0 + r) * NROW + (k0 + kk)) * CZ + c0))[c4];
            bs4[lin] = ((const float4*)(g_b +
                        ((size_t)(j0 + r) * NROW + (k0 + kk)) * CZ + c0))[c4];
        }
        __syncthreads();

#pragma unroll
        for (int kk = 0; kk < 4; ++kk) {
            float4 af[4];
#pragma unroll
            for (int ii = 0; ii < 4; ++ii)
                af[ii] = as4[((qi * 4 + ii) * 4 + kk) * 8 + g4];
            float4 bf[8];
#pragma unroll
            for (int jj = 0; jj < 8; ++jj)
                bf[jj] = bs4[((qj * 8 + jj) * 4 + kk) * 8 + g4];
#pragma unroll
            for (int ii = 0; ii < 4; ++ii)
#pragma unroll
                for (int jj = 0; jj < 8; ++jj) {
                    acc[ii][jj].x += af[ii].x * bf[jj].x;
                    acc[ii][jj].y += af[ii].y * bf[jj].y;
                    acc[ii][jj].z += af[ii].z * bf[jj].z;
                    acc[ii][jj].w += af[ii].w * bf[jj].w;
                }
        }
        __syncthreads();
    }

#pragma unroll
    for (int ii = 0; ii < 4; ++ii) {
        size_t i = (size_t)(i0 + qi * 4 + ii);
#pragma unroll
        for (int jj = 0; jj < 8; ++jj) {
            size_t j = (size_t)(j0 + qj * 8 + jj);
            *(float4*)(g_t + (i * NROW + j) * CZ + c0 + g4 * 4) = acc[ii][jj];
        }
    }
}

// ============================================================================
// final_kernel: out = g * (LN(t) @ w_z + b_z)
// ============================================================================
__global__ __launch_bounds__(256) void final_kernel(
    const float* __restrict__ lnw, const float* __restrict__ lnb,
    const float* __restrict__ w_z, const float* __restrict__ b_z,
    float* __restrict__ out)
{
    __shared__ float xs[32][CZ];
    __shared__ float ws[32][CZ];

    const int tid  = threadIdx.x;
    const int row0 = blockIdx.x * 32;

#pragma unroll
    for (int v = 0; v < 4; ++v) {
        int lin = v * 256 + tid;
        int r = lin >> 5, c4 = lin & 31;
        ((float4*)&xs[r][0])[c4] =
            ((const float4*)(g_t + (size_t)(row0 + r) * CZ))[c4];
    }
    __syncthreads();

    {
        const int lane = tid & 31, wid = tid >> 5;
        float lw0 = lnw[lane], lw1 = lnw[lane + 32], lw2 = lnw[lane + 64], lw3 = lnw[lane + 96];
        float lb0 = lnb[lane], lb1 = lnb[lane + 32], lb2 = lnb[lane + 64], lb3 = lnb[lane + 96];
#pragma unroll
        for (int r = 0; r < 4; ++r) {
            int row = wid * 4 + r;
            float x0 = xs[row][lane],      x1 = xs[row][lane + 32];
            float x2 = xs[row][lane + 64], x3 = xs[row][lane + 96];
            float m = warp_sum(x0 + x1 + x2 + x3) * (1.0f / 128.0f);
            float d0 = x0 - m, d1 = x1 - m, d2 = x2 - m, d3 = x3 - m;
            float var = warp_sum(d0 * d0 + d1 * d1 + d2 * d2 + d3 * d3) * (1.0f / 128.0f);
            float rs = rsqrtf(var + 1e-5f);
            xs[row][lane]      = d0 * rs * lw0 + lb0;
            xs[row][lane + 32] = d1 * rs * lw1 + lb1;
            xs[row][lane + 64] = d2 * rs * lw2 + lb2;
            xs[row][lane + 96] = d3 * rs * lw3 + lb3;
        }
    }
    __syncthreads();

    const int tc = tid & 31;
    const int tr = tid >> 5;

    float acc[4][4];
#pragma unroll
    for (int rr = 0; rr < 4; ++rr)
#pragma unroll
        for (int cc = 0; cc < 4; ++cc) acc[rr][cc] = 0.0f;

#pragma unroll 1
    for (int kc = 0; kc < 4; ++kc) {
#pragma unroll
        for (int v = 0; v < 4; ++v) {
            int lin = v * 256 + tid;
            int r = lin >> 5, c4 = lin & 31;
            ((float4*)&ws[r][0])[c4] =
                ((const float4*)(w_z + (size_t)(kc * 32 + r) * CZ))[c4];
        }
        __syncthreads();
#pragma unroll
        for (int k = 0; k < 32; ++k) {
            float4 wf = ((const float4*)&ws[k][0])[tc];
#pragma unroll
            for (int rr = 0; rr < 4; ++rr) {
                float xv = xs[tr * 4 + rr][kc * 32 + k];
                acc[rr][0] += xv * wf.x;
                acc[rr][1] += xv * wf.y;
                acc[rr][2] += xv * wf.z;
                acc[rr][3] += xv * wf.w;
            }
        }
        __syncthreads();
    }

    const int c = tc * 4;
    float4 bz = *(const float4*)(b_z + c);
#pragma unroll
    for (int rr = 0; rr < 4; ++rr) {
        size_t row = (size_t)(row0 + tr * 4 + rr);
        float4 gv = *(const float4*)(g_g + row * CZ + c);
        float4 o;
        o.x = gv.x * (acc[rr][0] + bz.x);
        o.y = gv.y * (acc[rr][1] + bz.y);
        o.z = gv.z * (acc[rr][2] + bz.z);
        o.w = gv.w * (acc[rr][3] + bz.w);
        *(float4*)(out + row * CZ + c) = o;
    }
}

// ============================================================================
// kernel_launch
// Inputs (metadata order): z, ln_in_w, ln_in_b, ln_out_w, ln_out_b,
//   w_ap, b_ap, w_ag, b_ag, w_bp, b_bp, w_bg, b_bg, w_g, b_g, w_z, b_z
// ============================================================================
extern "C" void kernel_launch(void* const* d_in, const int* in_sizes, int n_in,
                              void* d_out, int out_size)
{
    const float* z        = (const float*)d_in[0];
    const float* ln_in_w  = (const float*)d_in[1];
    const float* ln_in_b  = (const float*)d_in[2];
    const float* ln_out_w = (const float*)d_in[3];
    const float* ln_out_b = (const float*)d_in[4];
    const float* w_ap     = (const float*)d_in[5];
    const float* b_ap     = (const float*)d_in[6];
    const float* w_ag     = (const float*)d_in[7];
    const float* b_ag     = (const float*)d_in[8];
    const float* w_bp     = (const float*)d_in[9];
    const float* b_bp     = (const float*)d_in[10];
    const float* w_bg     = (const float*)d_in[11];
    const float* b_bg     = (const float*)d_in[12];
    const float* w_g      = (const float*)d_in[13];
    const float* b_g      = (const float*)d_in[14];
    const float* w_z      = (const float*)d_in[15];
    const float* b_z      = (const float*)d_in[16];
    float* out = (float*)d_out;

    const int nblk = NPAIR / 32;  // 8192

    proj_kernel<<<nblk, 256>>>(z, ln_in_w, ln_in_b, w_ap, b_ap, w_ag, b_ag, 0);
    proj_kernel<<<nblk, 256>>>(z, ln_in_w, ln_in_b, w_bp, b_bp, w_bg, b_bg, 1);
    proj_kernel<<<nblk, 256>>>(z, ln_in_w, ln_in_b, w_g,  b_g,  w_g,  b_g,  2);

    dim3 tgrid(NROW / 32, NROW / 32, CZ / 32);  // (16,16,4)
    tri_kernel<<<tgrid, 256>>>();

    final_kernel<<<nblk, 256>>>(ln_out_w, ln_out_b, w_z, b_z, out);
}

// round 4
// speedup vs baseline: 2.2599x; 2.2468x over previous
#include <cuda_runtime.h>
#include <math.h>

#define NROW 512
#define CZ   128
#define NPAIR (NROW * NROW) /* 262144 */

typedef unsigned int u32;

// ---------------- device scratch (no runtime allocation) ----------------
__device__ float g_A[(size_t)CZ * NPAIR];   // a, layout [c][i*512+k]
__device__ float g_B[(size_t)CZ * NPAIR];   // b, layout [c][j*512+k]
__device__ float g_G[(size_t)CZ * NPAIR];   // gate g, layout [c][pair]
__device__ float g_T[(size_t)CZ * NPAIR];   // t, layout [c][i*512+j]
__device__ float g_wt[6 * 128 * 128];       // transposed tf32 weights [n][k]
// order: 0 w_ap, 1 w_ag, 2 w_bp, 3 w_bg, 4 w_g, 5 w_z

// ---------------- helpers ----------------
__device__ __forceinline__ float tf32r(float x) {
    float r;
    asm("cvt.rna.tf32.f32 %0, %1;" : "=f"(r) : "f"(x));
    return r;
}
__device__ __forceinline__ float wsum(float v) {
#pragma unroll
    for (int o = 16; o; o >>= 1) v += __shfl_xor_sync(0xffffffffu, v, o);
    return v;
}
__device__ __forceinline__ float sigm(float x) {
    return 1.0f / (1.0f + __expf(-x));
}

// mma.sync m16n8k8 tf32: D += A(row) x B(col); acc 4 f32, A 4 b32, B 2 b32
__device__ __forceinline__ void mma8(float* d, const u32* a, const u32* b) {
    asm volatile(
        "mma.sync.aligned.m16n8k8.row.col.f32.tf32.tf32.f32 "
        "{%0,%1,%2,%3}, {%4,%5,%6,%7}, {%8,%9}, {%0,%1,%2,%3};"
        : "+f"(d[0]), "+f"(d[1]), "+f"(d[2]), "+f"(d[3])
        : "r"(a[0]), "r"(a[1]), "r"(a[2]), "r"(a[3]), "r"(b[0]), "r"(b[1]));
}

// 128x(64 cols per warp)x128 GEMM step over whole K=128, A row-major [132],
// B as [n][132]. acc[2][8][4].
__device__ __forceinline__ void gemm_k128(const float* __restrict__ As,
                                          const float* __restrict__ Ws,
                                          int m0, int n0, int g, int t,
                                          float acc[2][8][4]) {
#pragma unroll 4
    for (int ks = 0; ks < 16; ++ks) {
        const int k0 = ks * 8;
        u32 af[2][4];
#pragma unroll
        for (int mt = 0; mt < 2; ++mt) {
            const float* ap = As + (m0 + mt * 16 + g) * 132 + k0 + t;
            af[mt][0] = __float_as_uint(ap[0]);
            af[mt][1] = __float_as_uint(ap[8 * 132]);
            af[mt][2] = __float_as_uint(ap[4]);
            af[mt][3] = __float_as_uint(ap[8 * 132 + 4]);
        }
#pragma unroll
        for (int nt = 0; nt < 8; ++nt) {
            const float* bp = Ws + (n0 + nt * 8 + g) * 132 + k0 + t;
            u32 bf[2] = { __float_as_uint(bp[0]), __float_as_uint(bp[4]) };
            mma8(acc[0][nt], af[0], bf);
            mma8(acc[1][nt], af[1], bf);
        }
    }
}

// ============================================================================
// prep: transpose + tf32-round the 6 weight matrices into g_wt[img][n*128+k]
// ============================================================================
__global__ void prep_w(const float* __restrict__ wap, const float* __restrict__ wag,
                       const float* __restrict__ wbp, const float* __restrict__ wbg,
                       const float* __restrict__ wg,  const float* __restrict__ wz) {
    int img = blockIdx.y;
    int lin = blockIdx.x * 256 + threadIdx.x;  // n*128+k
    int n = lin >> 7, k = lin & 127;
    const float* s;
    switch (img) {
        case 0: s = wap; break; case 1: s = wag; break;
        case 2: s = wbp; break; case 3: s = wbg; break;
        case 4: s = wg;  break; default: s = wz; break;
    }
    g_wt[img * 16384 + lin] = tf32r(s[k * 128 + n]);
}

// ============================================================================
// shared LN: 8 warps x 16 rows -> As[128][132] tf32
// ============================================================================
__device__ __forceinline__ void ln_tile(const float* __restrict__ z, size_t pair0,
                                        float* __restrict__ As,
                                        const float* __restrict__ lnw,
                                        const float* __restrict__ lnb,
                                        int wid, int lane) {
    float4 lw = ((const float4*)lnw)[lane];
    float4 lb = ((const float4*)lnb)[lane];
#pragma unroll 2
    for (int r = 0; r < 16; ++r) {
        int row = wid * 16 + r;
        float4 x = ((const float4*)(z + (pair0 + row) * (size_t)CZ))[lane];
        float m = wsum(x.x + x.y + x.z + x.w) * (1.0f / 128.0f);
        float dx = x.x - m, dy = x.y - m, dz = x.z - m, dw = x.w - m;
        float var = wsum(dx * dx + dy * dy + dz * dz + dw * dw) * (1.0f / 128.0f);
        float rs = rsqrtf(var + 1e-5f);
        float* o = As + row * 132 + lane * 4;
        o[0] = tf32r(dx * rs * lw.x + lb.x);
        o[1] = tf32r(dy * rs * lw.y + lb.y);
        o[2] = tf32r(dz * rs * lw.z + lb.z);
        o[3] = tf32r(dw * rs * lw.w + lb.w);
    }
}

__device__ __forceinline__ void load_w(float* __restrict__ Ws, int widx, int tid) {
    const float4* src = (const float4*)(g_wt + widx * 16384);
#pragma unroll 4
    for (int it = 0; it < 16; ++it) {
        int lin = it * 256 + tid;           // 0..4095 float4
        int n = lin >> 5, k4 = lin & 31;
        *(float4*)&Ws[n * 132 + k4 * 4] = src[lin];
    }
}

// ============================================================================
// proj_ab: dst[c][pair] = sigmoid(zn@Wg + bg) * (zn@Wp + bp)
// ============================================================================
__global__ __launch_bounds__(256, 1) void proj_ab_kernel(
    const float* __restrict__ z,
    const float* __restrict__ lnw, const float* __restrict__ lnb,
    int wp_idx, int wg_idx,
    const float* __restrict__ bp, const float* __restrict__ bg,
    int dst_sel)
{
    extern __shared__ float sm[];
    float* As = sm;                // 128*132
    float* Ws = sm + 128 * 132;    // 128*132
    const int tid = threadIdx.x;
    const int wid = tid >> 5, lane = tid & 31;
    const int g = lane >> 2, t = lane & 3;
    const int m0 = (wid & 3) * 32, n0 = (wid >> 2) * 64;
    const size_t pair0 = (size_t)blockIdx.x * 128;
    float* __restrict__ dst = dst_sel ? g_B : g_A;

    ln_tile(z, pair0, As, lnw, lnb, wid, lane);
    load_w(Ws, wg_idx, tid);
    __syncthreads();

    float accg[2][8][4];
#pragma unroll
    for (int i = 0; i < 2; ++i)
#pragma unroll
        for (int j = 0; j < 8; ++j)
#pragma unroll
            for (int q = 0; q < 4; ++q) accg[i][j][q] = 0.f;
    gemm_k128(As, Ws, m0, n0, g, t, accg);
    __syncthreads();

    load_w(Ws, wp_idx, tid);
    __syncthreads();

    float accp[2][8][4];
#pragma unroll
    for (int i = 0; i < 2; ++i)
#pragma unroll
        for (int j = 0; j < 8; ++j)
#pragma unroll
            for (int q = 0; q < 4; ++q) accp[i][j][q] = 0.f;
    gemm_k128(As, Ws, m0, n0, g, t, accp);

#pragma unroll
    for (int mt = 0; mt < 2; ++mt) {
        int r = m0 + mt * 16 + g;
#pragma unroll
        for (int nt = 0; nt < 8; ++nt) {
            int c = n0 + nt * 8 + 2 * t;
            float2 bgv = *(const float2*)(bg + c);
            float2 bpv = *(const float2*)(bp + c);
            float* d0 = dst + (size_t)c * NPAIR + pair0;
            float* d1 = dst + (size_t)(c + 1) * NPAIR + pair0;
            d0[r]     = tf32r(sigm(accg[mt][nt][0] + bgv.x) * (accp[mt][nt][0] + bpv.x));
            d1[r]     = tf32r(sigm(accg[mt][nt][1] + bgv.y) * (accp[mt][nt][1] + bpv.y));
            d0[r + 8] = tf32r(sigm(accg[mt][nt][2] + bgv.x) * (accp[mt][nt][2] + bpv.x));
            d1[r + 8] = tf32r(sigm(accg[mt][nt][3] + bgv.y) * (accp[mt][nt][3] + bpv.y));
        }
    }
}

// ============================================================================
// proj_g: g_G[c][pair] = sigmoid(zn@Wg + bg)
// ============================================================================
__global__ __launch_bounds__(256, 1) void proj_g_kernel(
    const float* __restrict__ z,
    const float* __restrict__ lnw, const float* __restrict__ lnb,
    const float* __restrict__ bg)
{
    extern __shared__ float sm[];
    float* As = sm;
    float* Ws = sm + 128 * 132;
    const int tid = threadIdx.x;
    const int wid = tid >> 5, lane = tid & 31;
    const int g = lane >> 2, t = lane & 3;
    const int m0 = (wid & 3) * 32, n0 = (wid >> 2) * 64;
    const size_t pair0 = (size_t)blockIdx.x * 128;

    ln_tile(z, pair0, As, lnw, lnb, wid, lane);
    load_w(Ws, 4, tid);
    __syncthreads();

    float acc[2][8][4];
#pragma unroll
    for (int i = 0; i < 2; ++i)
#pragma unroll
        for (int j = 0; j < 8; ++j)
#pragma unroll
            for (int q = 0; q < 4; ++q) acc[i][j][q] = 0.f;
    gemm_k128(As, Ws, m0, n0, g, t, acc);

#pragma unroll
    for (int mt = 0; mt < 2; ++mt) {
        int r = m0 + mt * 16 + g;
#pragma unroll
        for (int nt = 0; nt < 8; ++nt) {
            int c = n0 + nt * 8 + 2 * t;
            float2 bgv = *(const float2*)(bg + c);
            float* d0 = g_G + (size_t)c * NPAIR + pair0;
            float* d1 = g_G + (size_t)(c + 1) * NPAIR + pair0;
            d0[r]     = sigm(acc[mt][nt][0] + bgv.x);
            d1[r]     = sigm(acc[mt][nt][1] + bgv.y);
            d0[r + 8] = sigm(acc[mt][nt][2] + bgv.x);
            d1[r + 8] = sigm(acc[mt][nt][3] + bgv.y);
        }
    }
}

// ============================================================================
// tri: t[c][i][j] = sum_k a[c][i][k] * b[c][j][k]; 128x128 tile, K=512
// grid (jt=4, it=4, c=128), 256 threads.
// ============================================================================
__global__ __launch_bounds__(256, 2) void tri_kernel()
{
    extern __shared__ float sm[];
    float* As = sm;                // [128][68]
    float* Bs = sm + 128 * 68;     // [128][68]
    const int tid = threadIdx.x;
    const int wid = tid >> 5, lane = tid & 31;
    const int g = lane >> 2, t = lane & 3;
    const int m0 = (wid & 3) * 32, n0 = (wid >> 2) * 64;

    const int c  = blockIdx.z;
    const int i0 = blockIdx.y * 128;
    const int j0 = blockIdx.x * 128;
    const float* __restrict__ asrc = g_A + (size_t)c * NPAIR + (size_t)i0 * NROW;
    const float* __restrict__ bsrc = g_B + (size_t)c * NPAIR + (size_t)j0 * NROW;

    float acc[2][8][4];
#pragma unroll
    for (int i = 0; i < 2; ++i)
#pragma unroll
        for (int j = 0; j < 8; ++j)
#pragma unroll
            for (int q = 0; q < 4; ++q) acc[i][j][q] = 0.f;

#pragma unroll 1
    for (int kc = 0; kc < 8; ++kc) {
        const int kb = kc * 64;
#pragma unroll
        for (int it = 0; it < 8; ++it) {
            int lin = it * 256 + tid;     // 0..2047 float4
            int row = lin >> 4, k4 = lin & 15;
            *(float4*)&As[row * 68 + k4 * 4] =
                *(const float4*)(asrc + (size_t)row * NROW + kb + k4 * 4);
            *(float4*)&Bs[row * 68 + k4 * 4] =
                *(const float4*)(bsrc + (size_t)row * NROW + kb + k4 * 4);
        }
        __syncthreads();
#pragma unroll
        for (int ks = 0; ks < 8; ++ks) {
            const int k0 = ks * 8;
            u32 af[2][4];
#pragma unroll
            for (int mt = 0; mt < 2; ++mt) {
                const float* ap = As + (m0 + mt * 16 + g) * 68 + k0 + t;
                af[mt][0] = __float_as_uint(ap[0]);
                af[mt][1] = __float_as_uint(ap[8 * 68]);
                af[mt][2] = __float_as_uint(ap[4]);
                af[mt][3] = __float_as_uint(ap[8 * 68 + 4]);
            }
#pragma unroll
            for (int nt = 0; nt < 8; ++nt) {
                const float* bp = Bs + (n0 + nt * 8 + g) * 68 + k0 + t;
                u32 bf[2] = { __float_as_uint(bp[0]), __float_as_uint(bp[4]) };
                mma8(acc[0][nt], af[0], bf);
                mma8(acc[1][nt], af[1], bf);
            }
        }
        __syncthreads();
    }

    float* __restrict__ tdst = g_T + (size_t)c * NPAIR;
#pragma unroll
    for (int mt = 0; mt < 2; ++mt) {
        int r = i0 + m0 + mt * 16 + g;
#pragma unroll
        for (int nt = 0; nt < 8; ++nt) {
            int cl = j0 + n0 + nt * 8 + 2 * t;
            float2 v0 = make_float2(acc[mt][nt][0], acc[mt][nt][1]);
            float2 v1 = make_float2(acc[mt][nt][2], acc[mt][nt][3]);
            *(float2*)(tdst + (size_t)r * NROW + cl)       = v0;
            *(float2*)(tdst + (size_t)(r + 8) * NROW + cl) = v1;
        }
    }
}

// ============================================================================
// final: out[pair][cz] = g * (LN_c(t) @ Wz + bz)
// ============================================================================
__global__ __launch_bounds__(256, 1) void final_kernel(
    const float* __restrict__ lnw, const float* __restrict__ lnb,
    const float* __restrict__ bz, float* __restrict__ out)
{
    extern __shared__ float sm[];
    float* As = sm;                        // [128 c][136 pair] k-major
    float* Ws = As + 128 * 136;            // [128][132]
    float* MS = Ws + 128 * 132;            // [128]
    float* RS = MS + 128;                  // [128]
    float* PS = RS + 128;                  // [256]
    float* PQ = PS + 256;                  // [256]
    const int tid = threadIdx.x;
    const int wid = tid >> 5, lane = tid & 31;
    const int g = lane >> 2, t = lane & 3;
    const int m0 = (wid & 3) * 32, n0 = (wid >> 2) * 64;
    const size_t pair0 = (size_t)blockIdx.x * 128;

    load_w(Ws, 5, tid);

    // pass1: gather t (coalesced per c), partial stats per pair
    {
        const int p = tid & 127, ch = tid >> 7;
        float s = 0.f, q = 0.f;
#pragma unroll 4
        for (int cc = 0; cc < 64; ++cc) {
            int c = ch * 64 + cc;
            float v = g_T[(size_t)c * NPAIR + pair0 + p];
            As[c * 136 + p] = v;
            s += v; q += v * v;
        }
        PS[tid] = s; PQ[tid] = q;
    }
    __syncthreads();
    if (tid < 128) {
        float s = PS[tid] + PS[tid + 128];
        float q = PQ[tid] + PQ[tid + 128];
        float m = s * (1.0f / 128.0f);
        MS[tid] = m;
        RS[tid] = rsqrtf(fmaxf(q * (1.0f / 128.0f) - m * m, 0.f) + 1e-5f);
    }
    __syncthreads();

    // pass2: normalize in place (per-pair stats, per-c scale), tf32 round
#pragma unroll 2
    for (int it = 0; it < 16; ++it) {
        int c = wid * 16 + it;
        float lw = __ldg(lnw + c), lb = __ldg(lnb + c);
#pragma unroll
        for (int sg = 0; sg < 4; ++sg) {
            int p = sg * 32 + lane;
            float x = As[c * 136 + p];
            As[c * 136 + p] = tf32r((x - MS[p]) * RS[p] * lw + lb);
        }
    }
    __syncthreads();

    float acc[2][8][4];
#pragma unroll
    for (int i = 0; i < 2; ++i)
#pragma unroll
        for (int j = 0; j < 8; ++j)
#pragma unroll
            for (int q = 0; q < 4; ++q) acc[i][j][q] = 0.f;

    // GEMM: A k-major [c][136]
#pragma unroll 4
    for (int ks = 0; ks < 16; ++ks) {
        const int k0 = ks * 8;
        u32 af[2][4];
#pragma unroll
        for (int mt = 0; mt < 2; ++mt) {
            const float* ap = As + (k0 + t) * 136 + m0 + mt * 16 + g;
            af[mt][0] = __float_as_uint(ap[0]);
            af[mt][1] = __float_as_uint(ap[8]);
            af[mt][2] = __float_as_uint(ap[4 * 136]);
            af[mt][3] = __float_as_uint(ap[4 * 136 + 8]);
        }
#pragma unroll
        for (int nt = 0; nt < 8; ++nt) {
            const float* bp = Ws + (n0 + nt * 8 + g) * 132 + k0 + t;
            u32 bf[2] = { __float_as_uint(bp[0]), __float_as_uint(bp[4]) };
            mma8(acc[0][nt], af[0], bf);
            mma8(acc[1][nt], af[1], bf);
        }
    }

#pragma unroll
    for (int mt = 0; mt < 2; ++mt) {
        int r = m0 + mt * 16 + g;
#pragma unroll
        for (int nt = 0; nt < 8; ++nt) {
            int c = n0 + nt * 8 + 2 * t;
            float2 bzv = *(const float2*)(bz + c);
            float gv00 = g_G[(size_t)c * NPAIR + pair0 + r];
            float gv01 = g_G[(size_t)(c + 1) * NPAIR + pair0 + r];
            float gv10 = g_G[(size_t)c * NPAIR + pair0 + r + 8];
            float gv11 = g_G[(size_t)(c + 1) * NPAIR + pair0 + r + 8];
            float2 o0 = make_float2(gv00 * (acc[mt][nt][0] + bzv.x),
                                    gv01 * (acc[mt][nt][1] + bzv.y));
            float2 o1 = make_float2(gv10 * (acc[mt][nt][2] + bzv.x),
                                    gv11 * (acc[mt][nt][3] + bzv.y));
            *(float2*)(out + (pair0 + r) * (size_t)CZ + c)     = o0;
            *(float2*)(out + (pair0 + r + 8) * (size_t)CZ + c) = o1;
        }
    }
}

// ============================================================================
// kernel_launch
// ============================================================================
extern "C" void kernel_launch(void* const* d_in, const int* in_sizes, int n_in,
                              void* d_out, int out_size)
{
    const float* z        = (const float*)d_in[0];
    const float* ln_in_w  = (const float*)d_in[1];
    const float* ln_in_b  = (const float*)d_in[2];
    const float* ln_out_w = (const float*)d_in[3];
    const float* ln_out_b = (const float*)d_in[4];
    const float* w_ap     = (const float*)d_in[5];
    const float* b_ap     = (const float*)d_in[6];
    const float* w_ag     = (const float*)d_in[7];
    const float* b_ag     = (const float*)d_in[8];
    const float* w_bp     = (const float*)d_in[9];
    const float* b_bp     = (const float*)d_in[10];
    const float* w_bg     = (const float*)d_in[11];
    const float* b_bg     = (const float*)d_in[12];
    const float* w_g      = (const float*)d_in[13];
    const float* b_g      = (const float*)d_in[14];
    const float* w_z      = (const float*)d_in[15];
    const float* b_z      = (const float*)d_in[16];
    float* out = (float*)d_out;

    const int PROJ_SMEM = 2 * 128 * 132 * 4;                 // 135168
    const int TRI_SMEM  = 2 * 128 * 68 * 4;                  // 69632
    const int FIN_SMEM  = (128 * 136 + 128 * 132 + 128 * 2 + 512) * 4; // 140288

    cudaFuncSetAttribute(proj_ab_kernel, cudaFuncAttributeMaxDynamicSharedMemorySize, PROJ_SMEM);
    cudaFuncSetAttribute(proj_g_kernel,  cudaFuncAttributeMaxDynamicSharedMemorySize, PROJ_SMEM);
    cudaFuncSetAttribute(tri_kernel,     cudaFuncAttributeMaxDynamicSharedMemorySize, TRI_SMEM);
    cudaFuncSetAttribute(final_kernel,   cudaFuncAttributeMaxDynamicSharedMemorySize, FIN_SMEM);

    dim3 pgrid(64, 6);
    prep_w<<<pgrid, 256>>>(w_ap, w_ag, w_bp, w_bg, w_g, w_z);

    const int nblk = NPAIR / 128;  // 2048
    proj_ab_kernel<<<nblk, 256, PROJ_SMEM>>>(z, ln_in_w, ln_in_b, 0, 1, b_ap, b_ag, 0);
    proj_ab_kernel<<<nblk, 256, PROJ_SMEM>>>(z, ln_in_w, ln_in_b, 2, 3, b_bp, b_bg, 1);
    proj_g_kernel<<<nblk, 256, PROJ_SMEM>>>(z, ln_in_w, ln_in_b, b_g);

    dim3 tgrid(4, 4, 128);
    tri_kernel<<<tgrid, 256, TRI_SMEM>>>();

    final_kernel<<<nblk, 256, FIN_SMEM>>>(ln_out_w, ln_out_b, b_z, out);
}